// round 1
// baseline (speedup 1.0000x reference)
#include <cuda_runtime.h>
#include <cuda_bf16.h>
#include <cstdint>
#include <cstddef>

// Problem constants
#define BB 4
#define SS 2048
#define DD 1024
#define HH 16
#define DKV 64          // DK == DV == 64
#define MTOK (BB*SS)    // 8192 tokens

// Scratch (allocations forbidden -> __device__ globals)
__device__ float g_q[MTOK * DD];    // [B,S,H,DK]  (token-major, head cols)
__device__ float g_k[MTOK * DD];
__device__ float g_v[MTOK * DD];
__device__ float g_att[MTOK * DD];  // attention output [B,S,H,DV]

// ---------------------------------------------------------------------------
// SGEMM: C[M,N] = A[M,K] * W[N,K]^T   (A row-major, W row-major "torch" weight)
// Block tile 128x128, k-tile 8, 256 threads, 8x8 micro-tile per thread.
// ---------------------------------------------------------------------------
__global__ __launch_bounds__(256) void sgemm_tn(
    const float* __restrict__ A, const float* __restrict__ W,
    float* __restrict__ C, int M, int N, int K)
{
    __shared__ float As[8][128];
    __shared__ float Ws[8][128];

    const int tid = threadIdx.x;
    const int lr  = tid >> 1;          // 0..127 : row within tile to load
    const int lc  = (tid & 1) << 2;    // 0 or 4 : k-col (float4)
    const int tx  = tid & 15;          // micro col group
    const int ty  = tid >> 4;          // micro row group
    const int bm  = blockIdx.y << 7;
    const int bn  = blockIdx.x << 7;

    const float* Ap = A + (size_t)(bm + lr) * K + lc;
    const float* Wp = W + (size_t)(bn + lr) * K + lc;

    float4 an = *(const float4*)Ap;
    float4 wn = *(const float4*)Wp;

    float acc[8][8];
#pragma unroll
    for (int i = 0; i < 8; ++i)
#pragma unroll
        for (int j = 0; j < 8; ++j) acc[i][j] = 0.f;

    for (int kt = 0; kt < K; kt += 8) {
        // stage current k-tile (transposed: As[k][row])
        As[lc + 0][lr] = an.x; As[lc + 1][lr] = an.y;
        As[lc + 2][lr] = an.z; As[lc + 3][lr] = an.w;
        Ws[lc + 0][lr] = wn.x; Ws[lc + 1][lr] = wn.y;
        Ws[lc + 2][lr] = wn.z; Ws[lc + 3][lr] = wn.w;
        __syncthreads();

        // prefetch next k-tile from gmem (overlaps with FFMA below)
        if (kt + 8 < K) {
            an = *(const float4*)(Ap + kt + 8);
            wn = *(const float4*)(Wp + kt + 8);
        }

#pragma unroll
        for (int k = 0; k < 8; ++k) {
            float a[8], b[8];
            *(float4*)&a[0] = *(const float4*)&As[k][ty << 3];
            *(float4*)&a[4] = *(const float4*)&As[k][(ty << 3) + 4];
            *(float4*)&b[0] = *(const float4*)&Ws[k][tx << 3];
            *(float4*)&b[4] = *(const float4*)&Ws[k][(tx << 3) + 4];
#pragma unroll
            for (int i = 0; i < 8; ++i)
#pragma unroll
                for (int j = 0; j < 8; ++j)
                    acc[i][j] += a[i] * b[j];
        }
        __syncthreads();
    }

#pragma unroll
    for (int i = 0; i < 8; ++i) {
        float* cp = C + (size_t)(bm + (ty << 3) + i) * N + bn + (tx << 3);
        *(float4*)cp       = make_float4(acc[i][0], acc[i][1], acc[i][2], acc[i][3]);
        *(float4*)(cp + 4) = make_float4(acc[i][4], acc[i][5], acc[i][6], acc[i][7]);
    }
}

// ---------------------------------------------------------------------------
// Fused attention: for each (b,h, 64-query tile), loop over 64-key tiles,
// online softmax, accumulate O in registers. q/k/v/o layout: [B,S,H,64].
// 256 threads: thread (ty,tx) owns 4 rows x 4 cols of every 64x64 tile.
// ---------------------------------------------------------------------------
__global__ __launch_bounds__(256) void attn_kernel(
    const float* __restrict__ Q, const float* __restrict__ Kx,
    const float* __restrict__ V, const int* __restrict__ mask,
    float* __restrict__ O)
{
    __shared__ float Qs[64][64];   // natural: Qs[row][k]
    __shared__ float KVs[64][64];  // K phase: KVs[k][col] (transposed); V phase: KVs[t][v]
    __shared__ float Ps[64][64];   // probabilities

    const int b  = blockIdx.z;
    const int h  = blockIdx.y;
    const int s0 = blockIdx.x << 6;
    const int tid = threadIdx.x;
    const int tx = tid & 15, ty = tid >> 4;
    const int R  = ty << 2;        // row base (0..60)
    const int Cc = tx << 2;        // col base (0..60)
    const int ROWSTRIDE = HH * DKV; // 1024 floats between tokens

    // load Q tile (coalesced float4)
    const float* qb = Q + ((size_t)(b * SS + s0) * HH + h) * DKV;
#pragma unroll
    for (int it = 0; it < 4; ++it) {
        int idx = tid + (it << 8);
        int r = idx >> 4, c4 = (idx & 15) << 2;
        *(float4*)&Qs[r][c4] = *(const float4*)(qb + (size_t)r * ROWSTRIDE + c4);
    }

    float m_i[4], l_i[4], acc[4][4];
#pragma unroll
    for (int i = 0; i < 4; ++i) {
        m_i[i] = -1e30f; l_i[i] = 0.f;
#pragma unroll
        for (int j = 0; j < 4; ++j) acc[i][j] = 0.f;
    }

    const int* mbase = mask + ((size_t)b * SS + s0) * SS;

    for (int t0 = 0; t0 < SS; t0 += 64) {
        __syncthreads();   // previous V reads complete before overwriting KVs

        // ---- load K tile, transposed into KVs[k][col] ----
        const float* kb = Kx + ((size_t)(b * SS + t0) * HH + h) * DKV;
#pragma unroll
        for (int it = 0; it < 4; ++it) {
            int idx = tid + (it << 8);
            int c = idx >> 4, k4 = (idx & 15) << 2;
            float4 val = *(const float4*)(kb + (size_t)c * ROWSTRIDE + k4);
            KVs[k4 + 0][c] = val.x; KVs[k4 + 1][c] = val.y;
            KVs[k4 + 2][c] = val.z; KVs[k4 + 3][c] = val.w;
        }
        __syncthreads();

        // ---- scores: S = Q * K^T ----
        float sc[4][4];
#pragma unroll
        for (int i = 0; i < 4; ++i)
#pragma unroll
            for (int j = 0; j < 4; ++j) sc[i][j] = 0.f;

#pragma unroll 8
        for (int kk = 0; kk < 64; ++kk) {
            float a0 = Qs[R + 0][kk], a1 = Qs[R + 1][kk];
            float a2 = Qs[R + 2][kk], a3 = Qs[R + 3][kk];
            float b0 = KVs[kk][Cc + 0], b1 = KVs[kk][Cc + 1];
            float b2 = KVs[kk][Cc + 2], b3 = KVs[kk][Cc + 3];
            sc[0][0] += a0 * b0; sc[0][1] += a0 * b1; sc[0][2] += a0 * b2; sc[0][3] += a0 * b3;
            sc[1][0] += a1 * b0; sc[1][1] += a1 * b1; sc[1][2] += a1 * b2; sc[1][3] += a1 * b3;
            sc[2][0] += a2 * b0; sc[2][1] += a2 * b1; sc[2][2] += a2 * b2; sc[2][3] += a2 * b3;
            sc[3][0] += a3 * b0; sc[3][1] += a3 * b1; sc[3][2] += a3 * b2; sc[3][3] += a3 * b3;
        }

        // ---- scale, mask, online softmax update ----
        const int* mrow = mbase + t0;
#pragma unroll
        for (int i = 0; i < 4; ++i) {
            float rm = -1e30f;
#pragma unroll
            for (int j = 0; j < 4; ++j) {
                float sv = sc[i][j] * 0.125f;   // 1/sqrt(64)
                if (mrow[(size_t)(R + i) * SS + Cc + j] == 0) sv = -1e10f;
                sc[i][j] = sv;
                rm = fmaxf(rm, sv);
            }
            rm = fmaxf(rm, __shfl_xor_sync(0xffffffffu, rm, 1));
            rm = fmaxf(rm, __shfl_xor_sync(0xffffffffu, rm, 2));
            rm = fmaxf(rm, __shfl_xor_sync(0xffffffffu, rm, 4));
            rm = fmaxf(rm, __shfl_xor_sync(0xffffffffu, rm, 8));
            float mnew = fmaxf(m_i[i], rm);
            float corr = __expf(m_i[i] - mnew);
            m_i[i] = mnew;

            float rs = 0.f;
#pragma unroll
            for (int j = 0; j < 4; ++j) {
                sc[i][j] = __expf(sc[i][j] - mnew);
                rs += sc[i][j];
            }
            rs += __shfl_xor_sync(0xffffffffu, rs, 1);
            rs += __shfl_xor_sync(0xffffffffu, rs, 2);
            rs += __shfl_xor_sync(0xffffffffu, rs, 4);
            rs += __shfl_xor_sync(0xffffffffu, rs, 8);
            l_i[i] = l_i[i] * corr + rs;
#pragma unroll
            for (int j = 0; j < 4; ++j) acc[i][j] *= corr;
        }

        __syncthreads();   // all score-phase KVs reads done

        // ---- stage P, load V tile (natural layout) ----
#pragma unroll
        for (int i = 0; i < 4; ++i)
#pragma unroll
            for (int j = 0; j < 4; ++j) Ps[R + i][Cc + j] = sc[i][j];

        const float* vb = V + ((size_t)(b * SS + t0) * HH + h) * DKV;
#pragma unroll
        for (int it = 0; it < 4; ++it) {
            int idx = tid + (it << 8);
            int r = idx >> 4, c4 = (idx & 15) << 2;
            *(float4*)&KVs[r][c4] = *(const float4*)(vb + (size_t)r * ROWSTRIDE + c4);
        }
        __syncthreads();

        // ---- O += P * V ----
#pragma unroll 8
        for (int t = 0; t < 64; ++t) {
            float a0 = Ps[R + 0][t], a1 = Ps[R + 1][t];
            float a2 = Ps[R + 2][t], a3 = Ps[R + 3][t];
            float b0 = KVs[t][Cc + 0], b1 = KVs[t][Cc + 1];
            float b2 = KVs[t][Cc + 2], b3 = KVs[t][Cc + 3];
            acc[0][0] += a0 * b0; acc[0][1] += a0 * b1; acc[0][2] += a0 * b2; acc[0][3] += a0 * b3;
            acc[1][0] += a1 * b0; acc[1][1] += a1 * b1; acc[1][2] += a1 * b2; acc[1][3] += a1 * b3;
            acc[2][0] += a2 * b0; acc[2][1] += a2 * b1; acc[2][2] += a2 * b2; acc[2][3] += a2 * b3;
            acc[3][0] += a3 * b0; acc[3][1] += a3 * b1; acc[3][2] += a3 * b2; acc[3][3] += a3 * b3;
        }
    }

    // ---- epilogue: normalize and store [B,S,H,DV] ----
    float* ob = O + ((size_t)(b * SS + s0) * HH + h) * DKV;
#pragma unroll
    for (int i = 0; i < 4; ++i) {
        float inv = __fdividef(1.f, l_i[i]);
        float4 o4 = make_float4(acc[i][0] * inv, acc[i][1] * inv,
                                acc[i][2] * inv, acc[i][3] * inv);
        *(float4*)(ob + (size_t)(R + i) * ROWSTRIDE + Cc) = o4;
    }
}

// ---------------------------------------------------------------------------
extern "C" void kernel_launch(void* const* d_in, const int* in_sizes, int n_in,
                              void* d_out, int out_size)
{
    const float* queries = (const float*)d_in[0];
    const float* keys    = (const float*)d_in[1];
    const float* values  = (const float*)d_in[2];
    const int*   mask    = (const int*)  d_in[3];
    const float* Wq      = (const float*)d_in[4];  // [H,DK,D] == [1024,1024]
    const float* Wk      = (const float*)d_in[5];
    const float* Wv      = (const float*)d_in[6];
    const float* Wo      = (const float*)d_in[7];  // [D, H*DV] == [1024,1024]
    float* out = (float*)d_out;

    float *gq, *gk, *gv, *go;
    cudaGetSymbolAddress((void**)&gq, g_q);
    cudaGetSymbolAddress((void**)&gk, g_k);
    cudaGetSymbolAddress((void**)&gv, g_v);
    cudaGetSymbolAddress((void**)&go, g_att);

    dim3 gg(DD / 128, MTOK / 128);  // (8, 64)

    // projections: [8192,1024] = X[8192,1024] @ W^T[1024,1024]
    sgemm_tn<<<gg, 256>>>(queries, Wq, gq, MTOK, DD, DD);
    sgemm_tn<<<gg, 256>>>(keys,    Wk, gk, MTOK, DD, DD);
    sgemm_tn<<<gg, 256>>>(values,  Wv, gv, MTOK, DD, DD);

    // fused attention
    attn_kernel<<<dim3(SS / 64, HH, BB), 256>>>(gq, gk, gv, mask, go);

    // output projection
    sgemm_tn<<<gg, 256>>>(go, Wo, out, MTOK, DD, DD);
}

// round 2
// speedup vs baseline: 2.6219x; 2.6219x over previous
#include <cuda_runtime.h>
#include <cuda_bf16.h>
#include <cstdint>
#include <cstddef>

#define BB 4
#define SS 2048
#define DD 1024
#define HH 16
#define MTOK (BB*SS)

// Scratch (no allocs allowed)
__device__ float g_q[MTOK * DD];
__device__ float g_k[MTOK * DD];
__device__ float g_v[MTOK * DD];
__device__ float g_att[MTOK * DD];

// ---------------------------------------------------------------------------
// helpers
// ---------------------------------------------------------------------------
__device__ __forceinline__ void mma16816(float* c, const uint32_t* a, const uint32_t* b) {
    asm volatile(
        "mma.sync.aligned.m16n8k16.row.col.f32.bf16.bf16.f32 "
        "{%0,%1,%2,%3},{%4,%5,%6,%7},{%8,%9},{%0,%1,%2,%3};"
        : "+f"(c[0]), "+f"(c[1]), "+f"(c[2]), "+f"(c[3])
        : "r"(a[0]), "r"(a[1]), "r"(a[2]), "r"(a[3]), "r"(b[0]), "r"(b[1]));
}

__device__ __forceinline__ uint32_t pack_bf16x2(float x, float y) {
    __nv_bfloat162 t = __floats2bfloat162_rn(x, y);
    return *reinterpret_cast<uint32_t*>(&t);
}

// split fp32 -> (bf16 hi, bf16 lo) and store 4 elements
__device__ __forceinline__ void store_split4(__nv_bfloat16* ph, __nv_bfloat16* pl, float4 v) {
    float f[4] = {v.x, v.y, v.z, v.w};
#pragma unroll
    for (int j = 0; j < 4; j += 2) {
        __nv_bfloat16 h0 = __float2bfloat16(f[j]);
        __nv_bfloat16 h1 = __float2bfloat16(f[j + 1]);
        float r0 = f[j]   - __bfloat162float(h0);
        float r1 = f[j+1] - __bfloat162float(h1);
        __nv_bfloat162 hv; hv.x = h0; hv.y = h1;
        *reinterpret_cast<uint32_t*>(ph + j) = *reinterpret_cast<uint32_t*>(&hv);
        *reinterpret_cast<uint32_t*>(pl + j) = pack_bf16x2(r0, r1);
    }
}

__device__ __forceinline__ void ldsm_x2_trans(uint32_t& r0, uint32_t& r1, const void* p) {
    uint32_t addr = (uint32_t)__cvta_generic_to_shared(p);
    asm volatile("ldmatrix.sync.aligned.m8n8.x2.trans.shared.b16 {%0,%1},[%2];"
                 : "=r"(r0), "=r"(r1) : "r"(addr));
}

// ---------------------------------------------------------------------------
// GEMM: C[M,N] = A[M,K] * W[N,K]^T, bf16 2-way split, 3 mmas per product.
// block 128x128, 8 warps (2x4), warp tile 64x32, k-tile 32.
// ---------------------------------------------------------------------------
#define AST 40   // smem row stride in bf16 elems (conflict-free)

__global__ __launch_bounds__(256, 2) void gemm_bf16x3(
    const float* __restrict__ A, const float* __restrict__ W,
    float* __restrict__ C, int M, int N, int K)
{
    __shared__ __align__(16) __nv_bfloat16 sAh[128 * AST];
    __shared__ __align__(16) __nv_bfloat16 sAl[128 * AST];
    __shared__ __align__(16) __nv_bfloat16 sWh[128 * AST];
    __shared__ __align__(16) __nv_bfloat16 sWl[128 * AST];

    const int tid  = threadIdx.x;
    const int lane = tid & 31, w = tid >> 5;
    const int g = lane >> 2, t4 = lane & 3;
    const int m0 = (w >> 2) * 64, n0 = (w & 3) * 32;
    const int bm = blockIdx.y * 128, bn = blockIdx.x * 128;

    float acc[4][4][4];
#pragma unroll
    for (int i = 0; i < 4; ++i)
#pragma unroll
        for (int j = 0; j < 4; ++j)
#pragma unroll
            for (int c = 0; c < 4; ++c) acc[i][j][c] = 0.f;

    for (int kt = 0; kt < K; kt += 32) {
        __syncthreads();
#pragma unroll
        for (int it = 0; it < 4; ++it) {
            int idx = it * 256 + tid;
            int r = idx >> 3, c4 = (idx & 7) << 2;
            float4 av = *(const float4*)(A + (size_t)(bm + r) * K + kt + c4);
            float4 wv = *(const float4*)(W + (size_t)(bn + r) * K + kt + c4);
            store_split4(&sAh[r * AST + c4], &sAl[r * AST + c4], av);
            store_split4(&sWh[r * AST + c4], &sWl[r * AST + c4], wv);
        }
        __syncthreads();

#pragma unroll
        for (int ks = 0; ks < 32; ks += 16) {
            uint32_t ah[4][4], al[4][4];
#pragma unroll
            for (int mt = 0; mt < 4; ++mt) {
                int rb = (m0 + mt * 16 + g) * AST + ks + 2 * t4;
                ah[mt][0] = *(const uint32_t*)&sAh[rb];
                ah[mt][1] = *(const uint32_t*)&sAh[rb + 8 * AST];
                ah[mt][2] = *(const uint32_t*)&sAh[rb + 8];
                ah[mt][3] = *(const uint32_t*)&sAh[rb + 8 * AST + 8];
                al[mt][0] = *(const uint32_t*)&sAl[rb];
                al[mt][1] = *(const uint32_t*)&sAl[rb + 8 * AST];
                al[mt][2] = *(const uint32_t*)&sAl[rb + 8];
                al[mt][3] = *(const uint32_t*)&sAl[rb + 8 * AST + 8];
            }
#pragma unroll
            for (int nt = 0; nt < 4; ++nt) {
                int rb = (n0 + nt * 8 + g) * AST + ks + 2 * t4;
                uint32_t bh[2] = { *(const uint32_t*)&sWh[rb], *(const uint32_t*)&sWh[rb + 8] };
                uint32_t bl[2] = { *(const uint32_t*)&sWl[rb], *(const uint32_t*)&sWl[rb + 8] };
#pragma unroll
                for (int mt = 0; mt < 4; ++mt) {
                    mma16816(acc[mt][nt], ah[mt], bh);
                    mma16816(acc[mt][nt], ah[mt], bl);
                    mma16816(acc[mt][nt], al[mt], bh);
                }
            }
        }
    }

#pragma unroll
    for (int mt = 0; mt < 4; ++mt)
#pragma unroll
        for (int nt = 0; nt < 4; ++nt) {
            int row = bm + m0 + mt * 16 + g;
            int col = bn + n0 + nt * 8 + 2 * t4;
            *(float2*)(C + (size_t)row * N + col) =
                make_float2(acc[mt][nt][0], acc[mt][nt][1]);
            *(float2*)(C + (size_t)(row + 8) * N + col) =
                make_float2(acc[mt][nt][2], acc[mt][nt][3]);
        }
}

// ---------------------------------------------------------------------------
// Fused attention, bf16x3 mma. Block = (b, h, 64-query tile), 4 warps,
// warp owns 16 query rows. K smem buffer is reused for P between phases.
// ---------------------------------------------------------------------------
#define TS 72    // smem row stride in bf16 elems

__global__ __launch_bounds__(128) void attn_bf16x3(
    const float* __restrict__ Q, const float* __restrict__ Kx,
    const float* __restrict__ V, const int* __restrict__ mask,
    float* __restrict__ O)
{
    extern __shared__ __align__(16) __nv_bfloat16 sm[];
    __nv_bfloat16* sQh = sm;
    __nv_bfloat16* sQl = sQh + 64 * TS;
    __nv_bfloat16* sKh = sQl + 64 * TS;   // reused for P (hi)
    __nv_bfloat16* sKl = sKh + 64 * TS;   // reused for P (lo)
    __nv_bfloat16* sVh = sKl + 64 * TS;
    __nv_bfloat16* sVl = sVh + 64 * TS;

    const int b = blockIdx.z, h = blockIdx.y, s0 = blockIdx.x * 64;
    const int tid = threadIdx.x, lane = tid & 31, w = tid >> 5;
    const int g = lane >> 2, t4 = lane & 3;
    const int m0 = w * 16;

    // stage Q tile (split)
    const float* qb = Q + (size_t)(b * SS + s0) * DD + h * 64;
#pragma unroll
    for (int it = 0; it < 8; ++it) {
        int idx = it * 128 + tid;
        int r = idx >> 4, c4 = (idx & 15) << 2;
        float4 v = *(const float4*)(qb + (size_t)r * DD + c4);
        store_split4(&sQh[r * TS + c4], &sQl[r * TS + c4], v);
    }

    float m_i[2] = {-1e30f, -1e30f}, l_i[2] = {0.f, 0.f};
    float oacc[8][4];
#pragma unroll
    for (int nt = 0; nt < 8; ++nt)
#pragma unroll
        for (int c = 0; c < 4; ++c) oacc[nt][c] = 0.f;

    const int* mrow0 = mask + ((size_t)b * SS + s0 + m0 + g) * SS;
    const int* mrow8 = mrow0 + (size_t)8 * SS;

    for (int t0 = 0; t0 < SS; t0 += 64) {
        __syncthreads();
        const float* kb = Kx + (size_t)(b * SS + t0) * DD + h * 64;
        const float* vb = V  + (size_t)(b * SS + t0) * DD + h * 64;
#pragma unroll
        for (int it = 0; it < 8; ++it) {
            int idx = it * 128 + tid;
            int r = idx >> 4, c4 = (idx & 15) << 2;
            float4 kv = *(const float4*)(kb + (size_t)r * DD + c4);
            store_split4(&sKh[r * TS + c4], &sKl[r * TS + c4], kv);
            float4 vv = *(const float4*)(vb + (size_t)r * DD + c4);
            store_split4(&sVh[r * TS + c4], &sVl[r * TS + c4], vv);
        }
        __syncthreads();

        // ---- scores S = Q K^T (16x64 per warp) ----
        float sc[8][4];
#pragma unroll
        for (int nt = 0; nt < 8; ++nt)
#pragma unroll
            for (int c = 0; c < 4; ++c) sc[nt][c] = 0.f;

#pragma unroll
        for (int ks = 0; ks < 64; ks += 16) {
            uint32_t qh[4], ql[4];
            int rb = (m0 + g) * TS + ks + 2 * t4;
            qh[0] = *(const uint32_t*)&sQh[rb];
            qh[1] = *(const uint32_t*)&sQh[rb + 8 * TS];
            qh[2] = *(const uint32_t*)&sQh[rb + 8];
            qh[3] = *(const uint32_t*)&sQh[rb + 8 * TS + 8];
            ql[0] = *(const uint32_t*)&sQl[rb];
            ql[1] = *(const uint32_t*)&sQl[rb + 8 * TS];
            ql[2] = *(const uint32_t*)&sQl[rb + 8];
            ql[3] = *(const uint32_t*)&sQl[rb + 8 * TS + 8];
#pragma unroll
            for (int nt = 0; nt < 8; ++nt) {
                int kb2 = (nt * 8 + g) * TS + ks + 2 * t4;
                uint32_t bh[2] = { *(const uint32_t*)&sKh[kb2], *(const uint32_t*)&sKh[kb2 + 8] };
                uint32_t bl[2] = { *(const uint32_t*)&sKl[kb2], *(const uint32_t*)&sKl[kb2 + 8] };
                mma16816(sc[nt], qh, bh);
                mma16816(sc[nt], qh, bl);
                mma16816(sc[nt], ql, bh);
            }
        }

        // ---- mask + scale + online softmax ----
        float mx0 = -1e30f, mx1 = -1e30f;
#pragma unroll
        for (int nt = 0; nt < 8; ++nt) {
            int tcol = t0 + nt * 8 + 2 * t4;
            int2 mk0 = *(const int2*)(mrow0 + tcol);
            int2 mk1 = *(const int2*)(mrow8 + tcol);
            sc[nt][0] = mk0.x ? sc[nt][0] * 0.125f : -1e10f;
            sc[nt][1] = mk0.y ? sc[nt][1] * 0.125f : -1e10f;
            sc[nt][2] = mk1.x ? sc[nt][2] * 0.125f : -1e10f;
            sc[nt][3] = mk1.y ? sc[nt][3] * 0.125f : -1e10f;
            mx0 = fmaxf(mx0, fmaxf(sc[nt][0], sc[nt][1]));
            mx1 = fmaxf(mx1, fmaxf(sc[nt][2], sc[nt][3]));
        }
        mx0 = fmaxf(mx0, __shfl_xor_sync(0xffffffffu, mx0, 1));
        mx0 = fmaxf(mx0, __shfl_xor_sync(0xffffffffu, mx0, 2));
        mx1 = fmaxf(mx1, __shfl_xor_sync(0xffffffffu, mx1, 1));
        mx1 = fmaxf(mx1, __shfl_xor_sync(0xffffffffu, mx1, 2));

        float mn0 = fmaxf(m_i[0], mx0), mn1 = fmaxf(m_i[1], mx1);
        float corr0 = __expf(m_i[0] - mn0), corr1 = __expf(m_i[1] - mn1);
        m_i[0] = mn0; m_i[1] = mn1;

        float sum0 = 0.f, sum1 = 0.f;
#pragma unroll
        for (int nt = 0; nt < 8; ++nt) {
            sc[nt][0] = __expf(sc[nt][0] - mn0);
            sc[nt][1] = __expf(sc[nt][1] - mn0);
            sc[nt][2] = __expf(sc[nt][2] - mn1);
            sc[nt][3] = __expf(sc[nt][3] - mn1);
            sum0 += sc[nt][0] + sc[nt][1];
            sum1 += sc[nt][2] + sc[nt][3];
        }
        sum0 += __shfl_xor_sync(0xffffffffu, sum0, 1);
        sum0 += __shfl_xor_sync(0xffffffffu, sum0, 2);
        sum1 += __shfl_xor_sync(0xffffffffu, sum1, 1);
        sum1 += __shfl_xor_sync(0xffffffffu, sum1, 2);
        l_i[0] = l_i[0] * corr0 + sum0;
        l_i[1] = l_i[1] * corr1 + sum1;
#pragma unroll
        for (int nt = 0; nt < 8; ++nt) {
            oacc[nt][0] *= corr0; oacc[nt][1] *= corr0;
            oacc[nt][2] *= corr1; oacc[nt][3] *= corr1;
        }

        __syncthreads();  // all warps done reading K before P overwrites it

        // ---- write P (split) into K buffers ----
#pragma unroll
        for (int nt = 0; nt < 8; ++nt) {
            int pr = (m0 + g) * TS + nt * 8 + 2 * t4;
            float e0 = sc[nt][0], e1 = sc[nt][1];
            float h0 = __bfloat162float(__float2bfloat16(e0));
            float h1 = __bfloat162float(__float2bfloat16(e1));
            *(uint32_t*)&sKh[pr] = pack_bf16x2(e0, e1);
            *(uint32_t*)&sKl[pr] = pack_bf16x2(e0 - h0, e1 - h1);
            float e2 = sc[nt][2], e3 = sc[nt][3];
            float h2 = __bfloat162float(__float2bfloat16(e2));
            float h3 = __bfloat162float(__float2bfloat16(e3));
            *(uint32_t*)&sKh[pr + 8 * TS] = pack_bf16x2(e2, e3);
            *(uint32_t*)&sKl[pr + 8 * TS] = pack_bf16x2(e2 - h2, e3 - h3);
        }
        __syncthreads();

        // ---- O += P V ----
#pragma unroll
        for (int ks = 0; ks < 64; ks += 16) {
            uint32_t ph[4], pl[4];
            int rb = (m0 + g) * TS + ks + 2 * t4;
            ph[0] = *(const uint32_t*)&sKh[rb];
            ph[1] = *(const uint32_t*)&sKh[rb + 8 * TS];
            ph[2] = *(const uint32_t*)&sKh[rb + 8];
            ph[3] = *(const uint32_t*)&sKh[rb + 8 * TS + 8];
            pl[0] = *(const uint32_t*)&sKl[rb];
            pl[1] = *(const uint32_t*)&sKl[rb + 8 * TS];
            pl[2] = *(const uint32_t*)&sKl[rb + 8];
            pl[3] = *(const uint32_t*)&sKl[rb + 8 * TS + 8];

            int vrow = ks + (lane & 15);
#pragma unroll
            for (int nt = 0; nt < 8; ++nt) {
                uint32_t vh[2], vl[2];
                ldsm_x2_trans(vh[0], vh[1], &sVh[vrow * TS + nt * 8]);
                ldsm_x2_trans(vl[0], vl[1], &sVl[vrow * TS + nt * 8]);
                mma16816(oacc[nt], ph, vh);
                mma16816(oacc[nt], ph, vl);
                mma16816(oacc[nt], pl, vh);
            }
        }
    }

    // ---- epilogue ----
    float inv0 = __fdividef(1.f, l_i[0]);
    float inv1 = __fdividef(1.f, l_i[1]);
    float* ob = O + (size_t)(b * SS + s0 + m0 + g) * DD + h * 64;
#pragma unroll
    for (int nt = 0; nt < 8; ++nt) {
        int col = nt * 8 + 2 * t4;
        *(float2*)(ob + col) = make_float2(oacc[nt][0] * inv0, oacc[nt][1] * inv0);
        *(float2*)(ob + (size_t)8 * DD + col) = make_float2(oacc[nt][2] * inv1, oacc[nt][3] * inv1);
    }
}

// ---------------------------------------------------------------------------
extern "C" void kernel_launch(void* const* d_in, const int* in_sizes, int n_in,
                              void* d_out, int out_size)
{
    const float* queries = (const float*)d_in[0];
    const float* keys    = (const float*)d_in[1];
    const float* values  = (const float*)d_in[2];
    const int*   mask    = (const int*)  d_in[3];
    const float* Wq      = (const float*)d_in[4];
    const float* Wk      = (const float*)d_in[5];
    const float* Wv      = (const float*)d_in[6];
    const float* Wo      = (const float*)d_in[7];
    float* out = (float*)d_out;

    float *gq, *gk, *gv, *go;
    cudaGetSymbolAddress((void**)&gq, g_q);
    cudaGetSymbolAddress((void**)&gk, g_k);
    cudaGetSymbolAddress((void**)&gv, g_v);
    cudaGetSymbolAddress((void**)&go, g_att);

    const int SMEM_ATTN = 6 * 64 * TS * (int)sizeof(__nv_bfloat16);
    cudaFuncSetAttribute(attn_bf16x3, cudaFuncAttributeMaxDynamicSharedMemorySize, SMEM_ATTN);

    dim3 gg(DD / 128, MTOK / 128);  // (8, 64)

    gemm_bf16x3<<<gg, 256>>>(queries, Wq, gq, MTOK, DD, DD);
    gemm_bf16x3<<<gg, 256>>>(keys,    Wk, gk, MTOK, DD, DD);
    gemm_bf16x3<<<gg, 256>>>(values,  Wv, gv, MTOK, DD, DD);

    attn_bf16x3<<<dim3(SS / 64, HH, BB), 128, SMEM_ATTN>>>(gq, gk, gv, mask, go);

    gemm_bf16x3<<<gg, 256>>>(go, Wo, out, MTOK, DD, DD);
}